// round 2
// baseline (speedup 1.0000x reference)
#include <cuda_runtime.h>
#include <cuda_bf16.h>
#include <cstdint>

// Problem constants (match reference)
#define U_DIM 20000
#define I_DIM 10000
#define K_DIM 64
#define B_DIM 4096

// Output region offsets (floats), in reference return order:
// (S_hat*mask)[U,I], (P*mask)[U,K], (bu*mask)[U,1], (Q*mask)[I,K], (bi*mask)[I]
#define OFF_SHAT   0LL
#define N_SHAT     (200000000LL)                 // U*I
#define OFF_UF     (OFF_SHAT + N_SHAT)           // 200,000,000
#define N_UF       (1280000LL)                   // U*K
#define OFF_UB     (OFF_UF + N_UF)               // 201,280,000
#define N_UB       (20000LL)
#define OFF_IF     (OFF_UB + N_UB)               // 201,300,000
#define N_IF       (640000LL)                    // I*K
#define OFF_IB     (OFF_IF + N_IF)               // 201,940,000
#define N_IB       (10000LL)
#define N_TOTAL    (OFF_IB + N_IB)               // 201,950,000

// ---------------------------------------------------------------------------
// Kernel 1: zero the output with wide stores. Extent comes from out_size at
// launch; vector part covers n4 float4s, tail kernel handles the remainder.
// ---------------------------------------------------------------------------
__global__ void mmf_zero_kernel(float4* __restrict__ out, long long n4) {
    long long idx = (long long)blockIdx.x * blockDim.x + threadIdx.x;
    if (idx < n4) {
        out[idx] = make_float4(0.f, 0.f, 0.f, 0.f);
    }
}

__global__ void mmf_zero_tail_kernel(float* __restrict__ out,
                                     long long start, long long n) {
    long long idx = start + (long long)blockIdx.x * blockDim.x + threadIdx.x;
    if (idx < n) out[idx] = 0.f;
}

// ---------------------------------------------------------------------------
// Kernel 2: scatter sparse non-zero values. One warp per batch entry b:
//   u = users_idx[b], i = items_idx[b]   (int32!)
//   S_hat[u,i]     = dot(P[u,:], Q[i,:]) + bu[u] + bi[i]
//   user_factor[u] = P[u,:]; user_bias[u] = bu[u]
//   item_factor[i] = Q[i,:]; item_bias[i] = bi[i]
// Duplicate u / i / (u,i) across batch entries write identical values.
// ---------------------------------------------------------------------------
__global__ void mmf_scatter_kernel(const float* __restrict__ P,       // [U,K]
                                   const float* __restrict__ Q,       // [I,K]
                                   const float* __restrict__ bu,      // [U]
                                   const float* __restrict__ bi,      // [I]
                                   const int* __restrict__ uidx,      // [B] i32
                                   const int* __restrict__ iidx,      // [B] i32
                                   float* __restrict__ out) {
    int gtid = blockIdx.x * blockDim.x + threadIdx.x;
    int warp = gtid >> 5;
    int lane = gtid & 31;
    if (warp >= B_DIM) return;

    long long u = (long long)uidx[warp];
    long long i = (long long)iidx[warp];

    const float* pu = P + u * K_DIM;
    const float* qi = Q + i * K_DIM;

    // K=64: 2 elements per lane
    float a0 = pu[lane];
    float a1 = pu[lane + 32];
    float b0 = qi[lane];
    float b1 = qi[lane + 32];

    float s = fmaf(a0, b0, a1 * b1);
    #pragma unroll
    for (int off = 16; off; off >>= 1)
        s += __shfl_xor_sync(0xffffffffu, s, off);

    float* out_uf = out + OFF_UF;
    float* out_ub = out + OFF_UB;
    float* out_if = out + OFF_IF;
    float* out_ib = out + OFF_IB;

    // Masked factor-row copies
    out_uf[u * K_DIM + lane]      = a0;
    out_uf[u * K_DIM + lane + 32] = a1;
    out_if[i * K_DIM + lane]      = b0;
    out_if[i * K_DIM + lane + 32] = b1;

    if (lane == 0) {
        float bias_u = bu[u];
        float bias_i = bi[i];
        out[u * (long long)I_DIM + i] = s + bias_u + bias_i;
        out_ub[u] = bias_u;
        out_ib[i] = bias_i;
    }
}

// ---------------------------------------------------------------------------
// Launch.
// inputs (metadata order): user_factor_weight [U,K] f32, item_factor_weight
// [I,K] f32, user_bias [U,1] f32, item_bias [I] f32,
// users_idx [B] int32 (JAX x64 disabled!), items_idx [B] int32
// ---------------------------------------------------------------------------
extern "C" void kernel_launch(void* const* d_in, const int* in_sizes, int n_in,
                              void* d_out, int out_size) {
    const float* P    = (const float*)d_in[0];
    const float* Q    = (const float*)d_in[1];
    const float* bu   = (const float*)d_in[2];
    const float* bi   = (const float*)d_in[3];
    const int*   uidx = (const int*)d_in[4];
    const int*   iidx = (const int*)d_in[5];
    float* out = (float*)d_out;

    // 1) zero the output (store-bandwidth bound: ~808 MB)
    const long long n_total = (long long)out_size;   // expected 201,950,000
    const long long n4 = n_total / 4;
    const int zthreads = 256;
    const long long zblocks = (n4 + zthreads - 1) / zthreads;
    mmf_zero_kernel<<<(unsigned)zblocks, zthreads>>>((float4*)out, n4);

    const long long tail_start = n4 * 4;
    if (tail_start < n_total) {
        mmf_zero_tail_kernel<<<1, 32>>>(out, tail_start, n_total);
    }

    // 2) scatter sparse values (one warp per batch entry)
    const int sthreads = 256;                     // 8 warps/block
    const int sblocks = (B_DIM * 32) / sthreads;  // 512
    mmf_scatter_kernel<<<sblocks, sthreads>>>(P, Q, bu, bi, uidx, iidx, out);
}